// round 15
// baseline (speedup 1.0000x reference)
#include <cuda_runtime.h>
#include <cuda_fp16.h>
#include <cstdint>

#define HD 128
#define NT 512
#define MTILE 32          // rows per tile
#define NTILES 4          // tiles per CTA (128 samples)
#define TSTRIDE 24576u    // per-tile A block: AVH +0, AVL +8192, ADH +16384
#define OFF_BH  98304u
#define OFF_BL  131072u
#define MAIN_SMEM 163840

#define S_UP   2048.0f                  // 2^11
#define S_DN   4.8828125e-4f            // 2^-11
#define S_DN2  2.384185791015625e-7f    // 2^-22

__device__ float2 g_head[3][2];
// pre-split swizzled weight tiles per iteration (iter = 2*branch + layer):
// levels H/L each 8192 u32 (32KB)
__device__ uint32_t g_Bsplit[6][2 * 8192];

// ---------------------------------------------------------------------------
// scaled fp16 split helpers
// ---------------------------------------------------------------------------
__device__ __forceinline__ float f16_rn(float x, uint32_t& bits) {
    __half h = __float2half_rn(x);
    bits = (uint32_t)__half_as_ushort(h);
    return __half2float(h);
}
__device__ __forceinline__ uint32_t pack_f16_pair(float a, float b) {
    uint32_t r;
    asm("cvt.rn.f16x2.f32 %0, %1, %2;" : "=r"(r) : "f"(b), "f"(a));
    return r;
}
// x ≈ h + l*2^-11 with l stored scaled by 2^11 (residual ~2^-24)
__device__ __forceinline__ void split2f_pair(float a, float b,
                                             uint32_t& h, uint32_t& l) {
    uint32_t ha, la, hb, lb;
    float f = f16_rn(a, ha); f16_rn((a - f) * S_UP, la);
    f = f16_rn(b, hb);       f16_rn((b - f) * S_UP, lb);
    h = ha | (hb << 16); l = la | (lb << 16);
}

// swizzled byte offset inside a [rows x 128 f16] tile (row stride 256B)
__device__ __forceinline__ uint32_t swz8(int row, int col8) {
    return (uint32_t)(row * 256) + ((uint32_t)((col8 ^ (row & 7))) << 4);
}

// ---------------------------------------------------------------------------
// ldmatrix / mma wrappers (baseline PTX, compute_103-safe)
// ---------------------------------------------------------------------------
__device__ __forceinline__ void ldmA(uint32_t f[4], uint32_t base, int r0, int ch, int lane) {
    int g = lane >> 3, i = lane & 7;
    int row = r0 + i + ((g & 1) << 3);
    int c   = ch + (g >> 1);
    uint32_t addr = base + swz8(row, c);
    asm volatile("ldmatrix.sync.aligned.m8n8.x4.shared.b16 {%0,%1,%2,%3}, [%4];"
                 : "=r"(f[0]), "=r"(f[1]), "=r"(f[2]), "=r"(f[3]) : "r"(addr));
}
__device__ __forceinline__ void ldmB(uint32_t f[4], uint32_t base, int n0, int ch, int lane) {
    int g = lane >> 3, i = lane & 7;
    int row = n0 + i + ((g >> 1) << 3);
    int c   = ch + (g & 1);
    uint32_t addr = base + swz8(row, c);
    asm volatile("ldmatrix.sync.aligned.m8n8.x4.shared.b16 {%0,%1,%2,%3}, [%4];"
                 : "=r"(f[0]), "=r"(f[1]), "=r"(f[2]), "=r"(f[3]) : "r"(addr));
}
__device__ __forceinline__ void mma_f16(float c[4], const uint32_t a[4],
                                        uint32_t b0, uint32_t b1) {
    asm volatile("mma.sync.aligned.m16n8k16.row.col.f32.f16.f16.f32 "
                 "{%0,%1,%2,%3}, {%4,%5,%6,%7}, {%8,%9}, {%0,%1,%2,%3};"
                 : "+f"(c[0]), "+f"(c[1]), "+f"(c[2]), "+f"(c[3])
                 : "r"(a[0]), "r"(a[1]), "r"(a[2]), "r"(a[3]), "r"(b0), "r"(b1));
}

// cp.async one 32KB level (2048 uint4) GMEM -> SMEM, 4 x 16B per thread
__device__ __forceinline__ void prefetch_level(const uint4* __restrict__ src,
                                               uint32_t dst, int tid) {
    #pragma unroll
    for (int i = 0; i < 4; ++i) {
        uint32_t d = dst + (uint32_t)(tid + i * NT) * 16u;
        const uint4* s = src + tid + i * NT;
        asm volatile("cp.async.cg.shared.global [%0], [%1], 16;"
                     :: "r"(d), "l"(s) : "memory");
    }
    asm volatile("cp.async.commit_group;" ::: "memory");
}
#define CP_WAIT0() asm volatile("cp.async.wait_group 0;" ::: "memory")

// 5-pass MMA over one 32-row tile, 16-col n-slab (nt<2):
// value 4 passes (hh, hl+lh, ll), tangent 1 pass (d·W_h).
__device__ __forceinline__ void mma_tile(uint32_t Abase, uint32_t BH, uint32_t BL,
                                         int m0, int n0, int lane,
                                         float acc1[2][4], float acc2[2][4],
                                         float acc3[2][4], float accd1[2][4])
{
    #pragma unroll
    for (int nt = 0; nt < 2; ++nt)
        #pragma unroll
        for (int q = 0; q < 4; ++q) {
            acc1[nt][q]=0.f; acc2[nt][q]=0.f; acc3[nt][q]=0.f; accd1[nt][q]=0.f;
        }
    #pragma unroll 2
    for (int ks = 0; ks < 8; ++ks) {
        const int ch = ks * 2;
        uint32_t avh[4], avl[4], adh[4];
        uint32_t bh[4], bl[4];
        ldmA(avh, Abase,          m0, ch, lane);
        ldmA(avl, Abase + 8192u,  m0, ch, lane);
        ldmA(adh, Abase + 16384u, m0, ch, lane);
        ldmB(bh, BH, n0, ch, lane);
        ldmB(bl, BL, n0, ch, lane);
        #pragma unroll
        for (int nt = 0; nt < 2; ++nt) {
            uint32_t b0h = bh[nt*2], b1h = bh[nt*2+1];
            uint32_t b0l = bl[nt*2], b1l = bl[nt*2+1];
            mma_f16(acc1[nt],  avh, b0h, b1h);
            mma_f16(accd1[nt], adh, b0h, b1h);
            mma_f16(acc2[nt],  avl, b0h, b1h);
            mma_f16(acc2[nt],  avh, b0l, b1l);
            mma_f16(acc3[nt],  avl, b0l, b1l);
        }
    }
}

// ---------------------------------------------------------------------------
// Prep kernel: split W2/W3 of every branch into swizzled scaled-fp16 tiles
// ---------------------------------------------------------------------------
__global__ void prep_kernel(const float* __restrict__ W2,
                            const float* __restrict__ W3)
{
    int iter = blockIdx.x;          // 0..5
    int b = iter >> 1, l = iter & 1;
    const float* W = (l ? W3 : W2) + b * HD * HD;
    char* dst = (char*)g_Bsplit[iter];
    for (int g = threadIdx.x; g < 2048; g += blockDim.x) {
        int j = g >> 4;
        int kg = (g & 15) * 8;
        float4 w0 = *(const float4*)(W + j * HD + kg);
        float4 w1 = *(const float4*)(W + j * HD + kg + 4);
        uint4 h, lo;
        split2f_pair(w0.x, w0.y, h.x, lo.x);
        split2f_pair(w0.z, w0.w, h.y, lo.y);
        split2f_pair(w1.x, w1.y, h.z, lo.z);
        split2f_pair(w1.z, w1.w, h.w, lo.w);
        uint32_t ao = swz8(j, kg >> 3);
        *(uint4*)(dst + ao)         = h;
        *(uint4*)(dst + 32768 + ao) = lo;
    }
}

// ---------------------------------------------------------------------------
// Head kernel (known-good fp32): (v, dv) at n=0,1 for all branches
// ---------------------------------------------------------------------------
#define HWS 129
__global__ void head_kernel(const float* __restrict__ t,
    const float* __restrict__ W1, const float* __restrict__ b1,
    const float* __restrict__ W2, const float* __restrict__ b2,
    const float* __restrict__ W3, const float* __restrict__ b3,
    const float* __restrict__ W4, const float* __restrict__ b4)
{
    extern __shared__ float hsm[];
    __shared__ float2 A[HD], B[HD];
    __shared__ float2 red[HD];
    const int j = threadIdx.x;
    float tv0 = t[0], tv1 = t[1];

    for (int b = 0; b < 3; ++b) {
        float w1 = W1[b*HD + j];
        float c1 = b1[b*HD + j];
        float c2 = b2[b*HD + j];
        float c3 = b3[b*HD + j];
        float w4 = W4[b*HD + j];
        for (int n = 0; n < 2; ++n) {
            float tn = (n == 0) ? tv0 : tv1;
            float pre = fmaf(tn, w1, c1);
            A[j] = make_float2(fmaxf(pre, 0.f), pre > 0.f ? w1 : 0.f);
            __syncthreads();
            for (int idx = j; idx < HD*HD; idx += HD) {
                int jj = idx >> 7, k = idx & 127;
                hsm[jj*HWS + k] = W2[b*HD*HD + idx];
            }
            __syncthreads();
            {
                float av = 0.f, ad = 0.f;
                #pragma unroll 8
                for (int k = 0; k < HD; ++k) {
                    float w = hsm[j*HWS + k]; float2 h = A[k];
                    av = fmaf(w, h.x, av); ad = fmaf(w, h.y, ad);
                }
                float p = av + c2;
                B[j] = make_float2(fmaxf(p, 0.f), p > 0.f ? ad : 0.f);
            }
            __syncthreads();
            for (int idx = j; idx < HD*HD; idx += HD) {
                int jj = idx >> 7, k = idx & 127;
                hsm[jj*HWS + k] = W3[b*HD*HD + idx];
            }
            __syncthreads();
            {
                float av = 0.f, ad = 0.f;
                #pragma unroll 8
                for (int k = 0; k < HD; ++k) {
                    float w = hsm[j*HWS + k]; float2 h = B[k];
                    av = fmaf(w, h.x, av); ad = fmaf(w, h.y, ad);
                }
                float p = av + c3;
                A[j] = make_float2(fmaxf(p, 0.f), p > 0.f ? ad : 0.f);
            }
            __syncthreads();
            red[j] = make_float2(w4 * A[j].x, w4 * A[j].y);
            __syncthreads();
            for (int s = 64; s > 0; s >>= 1) {
                if (j < s) { red[j].x += red[j+s].x; red[j].y += red[j+s].y; }
                __syncthreads();
            }
            if (j == 0) g_head[b][n] = make_float2(red[0].x + b4[b], red[0].y);
            __syncthreads();
        }
    }
}

// ---------------------------------------------------------------------------
// Main kernel: 128 samples/CTA as 4x32-row tiles sharing one staged B;
// 1 CTA/SM, 16 warps (2m x 8n grid). Value = 4-pass split GEMM; tangent = 1.
// ---------------------------------------------------------------------------
__global__ __launch_bounds__(NT, 1)
void main_kernel(const float* __restrict__ t,
    const float* __restrict__ W1, const float* __restrict__ b1,
    const float* __restrict__ b2, const float* __restrict__ b3,
    const float* __restrict__ W4, const float* __restrict__ b4,
    float* __restrict__ out, int N)
{
    extern __shared__ char smA[];
    const uint32_t sb = (uint32_t)__cvta_generic_to_shared(smA);

    const int tid  = threadIdx.x;
    const int lane = tid & 31;
    const int w    = tid >> 5;          // 0..15
    const int m0   = (w >> 3) * 16;     // row slab within a 32-row tile
    const int nw   = w & 7;
    const int n0   = nw * 16;           // 16-col slab

    const int base = blockIdx.x * (NTILES * MTILE);

    const uint32_t BH = sb + OFF_BH, BL = sb + OFF_BL;

    // initial prefetch of iteration 0 (branch 0, W2)
    {
        const uint4* src = (const uint4*)g_Bsplit[0];
        prefetch_level(src,        BH, tid);
        prefetch_level(src + 2048, BL, tid);
    }

    for (int b = 0; b < 3; ++b) {
        __syncthreads();    // guards prev-branch red reads vs A overwrite

        // ---- layer 1 (all tiles): elementwise -> A split buffers ----
        #pragma unroll
        for (int i = 0; i < 4; ++i) {
            int g = tid + i * NT;             // 0..2047
            int tile = g >> 9;
            int gg = g & 511;
            int r = gg >> 4, c0 = (gg & 15) * 8;
            float tv = __ldg(t + base + tile * MTILE + r);
            float4 w1a = __ldg((const float4*)(W1 + b*HD + c0));
            float4 w1b = __ldg((const float4*)(W1 + b*HD + c0 + 4));
            float4 c1a = __ldg((const float4*)(b1 + b*HD + c0));
            float4 c1b = __ldg((const float4*)(b1 + b*HD + c0 + 4));
            float wv[8] = {w1a.x,w1a.y,w1a.z,w1a.w,w1b.x,w1b.y,w1b.z,w1b.w};
            float cv[8] = {c1a.x,c1a.y,c1a.z,c1a.w,c1b.x,c1b.y,c1b.z,c1b.w};
            float hv[8], hd[8];
            #pragma unroll
            for (int q = 0; q < 8; ++q) {
                float pre = fmaf(tv, wv[q], cv[q]);
                bool mk = pre > 0.f;
                hv[q] = mk ? pre : 0.f;
                hd[q] = mk ? wv[q] : 0.f;
            }
            uint4 vh, vl, dh;
            split2f_pair(hv[0], hv[1], vh.x, vl.x);
            split2f_pair(hv[2], hv[3], vh.y, vl.y);
            split2f_pair(hv[4], hv[5], vh.z, vl.z);
            split2f_pair(hv[6], hv[7], vh.w, vl.w);
            dh.x = pack_f16_pair(hd[0], hd[1]);
            dh.y = pack_f16_pair(hd[2], hd[3]);
            dh.z = pack_f16_pair(hd[4], hd[5]);
            dh.w = pack_f16_pair(hd[6], hd[7]);
            uint32_t ao = swz8(r, c0 >> 3);
            char* tb = smA + tile * TSTRIDE;
            *(uint4*)(tb + ao)          = vh;
            *(uint4*)(tb + 8192u + ao)  = vl;
            *(uint4*)(tb + 16384u + ao) = dh;
        }
        if (b == 0) CP_WAIT0();
        __syncthreads();

        #pragma unroll 1
        for (int layer = 0; layer < 2; ++layer) {
            const int nxt = 2*b + layer + 1;
            const float* bias = (layer == 0) ? b2 : b3;

            float acc1[2][4], acc2[2][4], acc3[2][4], accd1[2][4];

            #pragma unroll 1
            for (int tile = 0; tile < NTILES; ++tile) {
                const uint32_t Abase = sb + (uint32_t)tile * TSTRIDE;
                mma_tile(Abase, BH, BL, m0, n0, lane, acc1, acc2, acc3, accd1);
                __syncthreads();   // all warps done reading A[tile] (and B at tile==3)

                if (tile == NTILES-1 && nxt < 6) {
                    const uint4* src = (const uint4*)g_Bsplit[nxt];
                    prefetch_level(src,        BH, tid);
                    prefetch_level(src + 2048, BL, tid);
                }

                if (layer == 0) {
                    // ---- epilogue 2: combine + bias + relu + resplit ----
                    #pragma unroll
                    for (int h = 0; h < 2; ++h) {
                        int row = m0 + 8*h + (lane >> 2);
                        #pragma unroll
                        for (int nt = 0; nt < 2; ++nt) {
                            int c = n0 + 8*nt + (lane & 3)*2;
                            float2 bb = __ldg((const float2*)(bias + b*HD + c));
                            float p0 = acc1[nt][2*h]   + fmaf(acc2[nt][2*h],   S_DN,
                                         fmaf(acc3[nt][2*h],   S_DN2, bb.x));
                            float p1 = acc1[nt][2*h+1] + fmaf(acc2[nt][2*h+1], S_DN,
                                         fmaf(acc3[nt][2*h+1], S_DN2, bb.y));
                            bool q0 = p0 > 0.f, q1 = p1 > 0.f;
                            float v0 = q0 ? p0 : 0.f, v1 = q1 ? p1 : 0.f;
                            float d0 = q0 ? accd1[nt][2*h]   : 0.f;
                            float d1 = q1 ? accd1[nt][2*h+1] : 0.f;
                            uint32_t vh, vl;
                            split2f_pair(v0, v1, vh, vl);
                            uint32_t dh = pack_f16_pair(d0, d1);
                            uint32_t ao = swz8(row, c >> 3) + ((c & 7) << 1);
                            char* tb = smA + tile * TSTRIDE;
                            *(uint32_t*)(tb + ao)          = vh;
                            *(uint32_t*)(tb + 8192u + ao)  = vl;
                            *(uint32_t*)(tb + 16384u + ao) = dh;
                        }
                    }
                } else {
                    // ---- epilogue 3: combine + bias + relu + dot(w4) ----
                    float2* red = (float2*)(smA + tile * TSTRIDE + 16384u);
                    #pragma unroll
                    for (int h = 0; h < 2; ++h) {
                        int row = m0 + 8*h + (lane >> 2);
                        float sv = 0.f, sd = 0.f;
                        #pragma unroll
                        for (int nt = 0; nt < 2; ++nt) {
                            int c = n0 + 8*nt + (lane & 3)*2;
                            float2 bb = __ldg((const float2*)(b3 + b*HD + c));
                            float2 ww = __ldg((const float2*)(W4 + b*HD + c));
                            float p0 = acc1[nt][2*h]   + fmaf(acc2[nt][2*h],   S_DN,
                                         fmaf(acc3[nt][2*h],   S_DN2, bb.x));
                            float p1 = acc1[nt][2*h+1] + fmaf(acc2[nt][2*h+1], S_DN,
                                         fmaf(acc3[nt][2*h+1], S_DN2, bb.y));
                            bool q0 = p0 > 0.f, q1 = p1 > 0.f;
                            sv = fmaf(q0 ? p0 : 0.f, ww.x, sv);
                            sv = fmaf(q1 ? p1 : 0.f, ww.y, sv);
                            sd = fmaf(q0 ? accd1[nt][2*h]   : 0.f, ww.x, sd);
                            sd = fmaf(q1 ? accd1[nt][2*h+1] : 0.f, ww.y, sd);
                        }
                        sv += __shfl_xor_sync(0xffffffffu, sv, 1);
                        sv += __shfl_xor_sync(0xffffffffu, sv, 2);
                        sd += __shfl_xor_sync(0xffffffffu, sd, 1);
                        sd += __shfl_xor_sync(0xffffffffu, sd, 2);
                        if ((lane & 3) == 0) red[row*8 + nw] = make_float2(sv, sd);
                    }
                }
            }
            CP_WAIT0();
            __syncthreads();   // A' / red writes + next B all in place

            if (layer == 1 && tid < NTILES * MTILE) {
                int tile = tid >> 5, rr = tid & 31;
                float2* red = (float2*)(smA + tile * TSTRIDE + 16384u);
                float v = 0.f, dv = 0.f;
                #pragma unroll
                for (int k = 0; k < 8; ++k) {
                    float2 p = red[rr*8 + k];
                    v += p.x; dv += p.y;
                }
                v += __ldg(b4 + b);
                float2 h0 = g_head[b][0];
                float2 h1 = g_head[b][1];
                float s = (b == 1) ? -1.f : 1.f;
                float d1 = h1.x - h0.x;
                float sg1 = (d1 > 0.f) ? 1.f : ((d1 < 0.f) ? -1.f : 0.f);
                float dsign1 = s * sg1 * h1.y;
                int n = base + tid;
                float d = v - h0.x;
                float vv, ds;
                if (n == 0) {
                    vv = 0.f;
                    ds = (dsign1 >= 0.f) ? fabsf(dv) : -fabsf(dv);
                } else {
                    float sg = (d > 0.f) ? 1.f : ((d < 0.f) ? -1.f : 0.f);
                    vv = s * fabsf(d);
                    ds = s * sg * dv;
                }
                out[b*N + n]       = vv;
                out[(3 + b)*N + n] = ds;
            }
        }
    }
}

// ---------------------------------------------------------------------------
extern "C" void kernel_launch(void* const* d_in, const int* in_sizes, int n_in,
                              void* d_out, int out_size)
{
    const float* t  = (const float*)d_in[0];
    const float* W1 = (const float*)d_in[1];
    const float* b1 = (const float*)d_in[2];
    const float* W2 = (const float*)d_in[3];
    const float* b2 = (const float*)d_in[4];
    const float* W3 = (const float*)d_in[5];
    const float* b3 = (const float*)d_in[6];
    const float* W4 = (const float*)d_in[7];
    const float* b4 = (const float*)d_in[8];
    float* out = (float*)d_out;
    const int N = in_sizes[0];

    const int HEAD_SMEM = HD * HWS * 4;

    cudaFuncSetAttribute(main_kernel, cudaFuncAttributeMaxDynamicSharedMemorySize, MAIN_SMEM);
    cudaFuncSetAttribute(head_kernel, cudaFuncAttributeMaxDynamicSharedMemorySize, HEAD_SMEM);

    prep_kernel<<<6, 256>>>(W2, W3);
    head_kernel<<<1, HD, HEAD_SMEM>>>(t, W1, b1, W2, b2, W3, b3, W4, b4);
    main_kernel<<<N / (NTILES * MTILE), NT, MAIN_SMEM>>>(t, W1, b1, b2, b3, W4, b4, out, N);
}

// round 16
// speedup vs baseline: 1.1432x; 1.1432x over previous
#include <cuda_runtime.h>
#include <cuda_fp16.h>
#include <cstdint>

#define HD 128
#define NT 256
#define MTILE 32          // rows per tile; 2 tiles per CTA (64 samples)

// byte offsets in dynamic smem
#define OFF_AVH0 0u
#define OFF_AVL0 8192u
#define OFF_ADH0 16384u
#define OFF_AVH1 24576u
#define OFF_AVL1 32768u
#define OFF_ADH1 40960u
#define OFF_BH   49152u
#define OFF_BL   81920u
#define MAIN_SMEM 114688

#define S_UP   2048.0f                  // 2^11
#define S_DN   4.8828125e-4f            // 2^-11
#define S_DN2  2.384185791015625e-7f    // 2^-22

__device__ float2 g_head[3][2];
// pre-split swizzled weight tiles per iteration (iter = 2*branch + layer):
// levels H/L each 8192 u32 (32KB)
__device__ uint32_t g_Bsplit[6][2 * 8192];

// ---------------------------------------------------------------------------
// scaled fp16 split helpers
// ---------------------------------------------------------------------------
__device__ __forceinline__ float f16_rn(float x, uint32_t& bits) {
    __half h = __float2half_rn(x);
    bits = (uint32_t)__half_as_ushort(h);
    return __half2float(h);
}
__device__ __forceinline__ uint32_t pack_f16_pair(float a, float b) {
    uint32_t r;
    asm("cvt.rn.f16x2.f32 %0, %1, %2;" : "=r"(r) : "f"(b), "f"(a));
    return r;
}
// x ≈ h + l*2^-11 with l stored scaled by 2^11 (residual ~2^-24)
__device__ __forceinline__ void split2f_pair(float a, float b,
                                             uint32_t& h, uint32_t& l) {
    uint32_t ha, la, hb, lb;
    float f = f16_rn(a, ha); f16_rn((a - f) * S_UP, la);
    f = f16_rn(b, hb);       f16_rn((b - f) * S_UP, lb);
    h = ha | (hb << 16); l = la | (lb << 16);
}

// swizzled byte offset inside a [rows x 128 f16] tile (row stride 256B)
__device__ __forceinline__ uint32_t swz8(int row, int col8) {
    return (uint32_t)(row * 256) + ((uint32_t)((col8 ^ (row & 7))) << 4);
}

// ---------------------------------------------------------------------------
// ldmatrix / mma wrappers (baseline PTX, compute_103-safe)
// ---------------------------------------------------------------------------
__device__ __forceinline__ void ldmA(uint32_t f[4], uint32_t base, int r0, int ch, int lane) {
    int g = lane >> 3, i = lane & 7;
    int row = r0 + i + ((g & 1) << 3);
    int c   = ch + (g >> 1);
    uint32_t addr = base + swz8(row, c);
    asm volatile("ldmatrix.sync.aligned.m8n8.x4.shared.b16 {%0,%1,%2,%3}, [%4];"
                 : "=r"(f[0]), "=r"(f[1]), "=r"(f[2]), "=r"(f[3]) : "r"(addr));
}
__device__ __forceinline__ void ldmB(uint32_t f[4], uint32_t base, int n0, int ch, int lane) {
    int g = lane >> 3, i = lane & 7;
    int row = n0 + i + ((g >> 1) << 3);
    int c   = ch + (g & 1);
    uint32_t addr = base + swz8(row, c);
    asm volatile("ldmatrix.sync.aligned.m8n8.x4.shared.b16 {%0,%1,%2,%3}, [%4];"
                 : "=r"(f[0]), "=r"(f[1]), "=r"(f[2]), "=r"(f[3]) : "r"(addr));
}
__device__ __forceinline__ void mma_f16(float c[4], const uint32_t a[4],
                                        uint32_t b0, uint32_t b1) {
    asm volatile("mma.sync.aligned.m16n8k16.row.col.f32.f16.f16.f32 "
                 "{%0,%1,%2,%3}, {%4,%5,%6,%7}, {%8,%9}, {%0,%1,%2,%3};"
                 : "+f"(c[0]), "+f"(c[1]), "+f"(c[2]), "+f"(c[3])
                 : "r"(a[0]), "r"(a[1]), "r"(a[2]), "r"(a[3]), "r"(b0), "r"(b1));
}

// cp.async one 32KB level (2048 uint4) GMEM -> SMEM, 8 x 16B per thread
__device__ __forceinline__ void prefetch_level(const uint4* __restrict__ src,
                                               uint32_t dst, int tid) {
    #pragma unroll
    for (int i = 0; i < 8; ++i) {
        uint32_t d = dst + (uint32_t)(tid + i * NT) * 16u;
        const uint4* s = src + tid + i * NT;
        asm volatile("cp.async.cg.shared.global [%0], [%1], 16;"
                     :: "r"(d), "l"(s) : "memory");
    }
    asm volatile("cp.async.commit_group;" ::: "memory");
}
#define CP_WAIT0() asm volatile("cp.async.wait_group 0;" ::: "memory")

// 5-pass MMA over one 32-row tile: value 4 passes (hh, hl+lh, ll),
// tangent 1 pass (d·W_h, fp16-rounded weights).
__device__ __forceinline__ void mma_tile(uint32_t AVH, uint32_t AVL, uint32_t ADH,
                                         uint32_t BH, uint32_t BL,
                                         int m0, int n0, int lane,
                                         float acc1[4][4], float acc2[4][4],
                                         float acc3[4][4], float accd1[4][4])
{
    #pragma unroll
    for (int nt = 0; nt < 4; ++nt)
        #pragma unroll
        for (int q = 0; q < 4; ++q) {
            acc1[nt][q]=0.f; acc2[nt][q]=0.f; acc3[nt][q]=0.f;
            accd1[nt][q]=0.f;
        }
    #pragma unroll 1
    for (int ks = 0; ks < 8; ++ks) {
        const int ch = ks * 2;
        uint32_t avh[4], avl[4], adh[4];
        uint32_t bh[2][4], bl[2][4];
        ldmA(avh, AVH, m0, ch, lane);
        ldmA(avl, AVL, m0, ch, lane);
        ldmA(adh, ADH, m0, ch, lane);
        ldmB(bh[0], BH, n0, ch, lane); ldmB(bh[1], BH, n0 + 16, ch, lane);
        ldmB(bl[0], BL, n0, ch, lane); ldmB(bl[1], BL, n0 + 16, ch, lane);
        #pragma unroll
        for (int nt = 0; nt < 4; ++nt) {
            uint32_t b0h = bh[nt>>1][(nt&1)*2], b1h = bh[nt>>1][(nt&1)*2+1];
            uint32_t b0l = bl[nt>>1][(nt&1)*2], b1l = bl[nt>>1][(nt&1)*2+1];
            mma_f16(acc1[nt],  avh, b0h, b1h);
            mma_f16(accd1[nt], adh, b0h, b1h);
            mma_f16(acc2[nt],  avl, b0h, b1h);
            mma_f16(acc2[nt],  avh, b0l, b1l);
            mma_f16(acc3[nt],  avl, b0l, b1l);
        }
    }
}

// ---------------------------------------------------------------------------
// Prep kernel: split W2/W3 of every branch into swizzled scaled-fp16 tiles
// ---------------------------------------------------------------------------
__global__ void prep_kernel(const float* __restrict__ W2,
                            const float* __restrict__ W3)
{
    int iter = blockIdx.x;          // 0..5
    int b = iter >> 1, l = iter & 1;
    const float* W = (l ? W3 : W2) + b * HD * HD;
    char* dst = (char*)g_Bsplit[iter];
    for (int g = threadIdx.x; g < 2048; g += blockDim.x) {
        int j = g >> 4;
        int kg = (g & 15) * 8;
        float4 w0 = *(const float4*)(W + j * HD + kg);
        float4 w1 = *(const float4*)(W + j * HD + kg + 4);
        uint4 h, lo;
        split2f_pair(w0.x, w0.y, h.x, lo.x);
        split2f_pair(w0.z, w0.w, h.y, lo.y);
        split2f_pair(w1.x, w1.y, h.z, lo.z);
        split2f_pair(w1.z, w1.w, h.w, lo.w);
        uint32_t ao = swz8(j, kg >> 3);
        *(uint4*)(dst + ao)         = h;
        *(uint4*)(dst + 32768 + ao) = lo;
    }
}

// ---------------------------------------------------------------------------
// Head kernel (known-good fp32): (v, dv) at n=0,1 for all branches
// ---------------------------------------------------------------------------
#define HWS 129
__global__ void head_kernel(const float* __restrict__ t,
    const float* __restrict__ W1, const float* __restrict__ b1,
    const float* __restrict__ W2, const float* __restrict__ b2,
    const float* __restrict__ W3, const float* __restrict__ b3,
    const float* __restrict__ W4, const float* __restrict__ b4)
{
    extern __shared__ float hsm[];
    __shared__ float2 A[HD], B[HD];
    __shared__ float2 red[HD];
    const int j = threadIdx.x;
    float tv0 = t[0], tv1 = t[1];

    for (int b = 0; b < 3; ++b) {
        float w1 = W1[b*HD + j];
        float c1 = b1[b*HD + j];
        float c2 = b2[b*HD + j];
        float c3 = b3[b*HD + j];
        float w4 = W4[b*HD + j];
        for (int n = 0; n < 2; ++n) {
            float tn = (n == 0) ? tv0 : tv1;
            float pre = fmaf(tn, w1, c1);
            A[j] = make_float2(fmaxf(pre, 0.f), pre > 0.f ? w1 : 0.f);
            __syncthreads();
            for (int idx = j; idx < HD*HD; idx += HD) {
                int jj = idx >> 7, k = idx & 127;
                hsm[jj*HWS + k] = W2[b*HD*HD + idx];
            }
            __syncthreads();
            {
                float av = 0.f, ad = 0.f;
                #pragma unroll 8
                for (int k = 0; k < HD; ++k) {
                    float w = hsm[j*HWS + k]; float2 h = A[k];
                    av = fmaf(w, h.x, av); ad = fmaf(w, h.y, ad);
                }
                float p = av + c2;
                B[j] = make_float2(fmaxf(p, 0.f), p > 0.f ? ad : 0.f);
            }
            __syncthreads();
            for (int idx = j; idx < HD*HD; idx += HD) {
                int jj = idx >> 7, k = idx & 127;
                hsm[jj*HWS + k] = W3[b*HD*HD + idx];
            }
            __syncthreads();
            {
                float av = 0.f, ad = 0.f;
                #pragma unroll 8
                for (int k = 0; k < HD; ++k) {
                    float w = hsm[j*HWS + k]; float2 h = B[k];
                    av = fmaf(w, h.x, av); ad = fmaf(w, h.y, ad);
                }
                float p = av + c3;
                A[j] = make_float2(fmaxf(p, 0.f), p > 0.f ? ad : 0.f);
            }
            __syncthreads();
            red[j] = make_float2(w4 * A[j].x, w4 * A[j].y);
            __syncthreads();
            for (int s = 64; s > 0; s >>= 1) {
                if (j < s) { red[j].x += red[j+s].x; red[j].y += red[j+s].y; }
                __syncthreads();
            }
            if (j == 0) g_head[b][n] = make_float2(red[0].x + b4[b], red[0].y);
            __syncthreads();
        }
    }
}

// ---------------------------------------------------------------------------
// Main kernel: 64 samples/CTA as 2x32-row tiles sharing one staged B;
// 2 CTAs/SM. Staged epilogues: results computed into registers BEFORE the
// post-MMA barrier; only SMEM stores happen after it.
// ---------------------------------------------------------------------------
__global__ __launch_bounds__(NT, 2)
void main_kernel(const float* __restrict__ t,
    const float* __restrict__ W1, const float* __restrict__ b1,
    const float* __restrict__ b2, const float* __restrict__ b3,
    const float* __restrict__ W4, const float* __restrict__ b4,
    float* __restrict__ out, int N)
{
    extern __shared__ char smA[];
    const uint32_t sb = (uint32_t)__cvta_generic_to_shared(smA);

    const int tid  = threadIdx.x;
    const int lane = tid & 31;
    const int w    = tid >> 5;          // 0..7
    const int m0   = (w >> 2) * 16;     // row slab within a 32-row tile
    const int wn   = w & 3;
    const int n0   = wn * 32;           // 32-col slab

    const int base = blockIdx.x * (2 * MTILE);

    const uint32_t AVH[2] = {sb + OFF_AVH0, sb + OFF_AVH1};
    const uint32_t AVL[2] = {sb + OFF_AVL0, sb + OFF_AVL1};
    const uint32_t ADH[2] = {sb + OFF_ADH0, sb + OFF_ADH1};
    const uint32_t BH = sb + OFF_BH, BL = sb + OFF_BL;
    float2* red0 = (float2*)(smA + OFF_ADH0);   // alias: dead after last MMA(t0)
    float2* red1 = (float2*)(smA + OFF_ADH1);

    // initial prefetch of iteration 0 (branch 0, W2)
    {
        const uint4* src = (const uint4*)g_Bsplit[0];
        prefetch_level(src,        BH, tid);
        prefetch_level(src + 2048, BL, tid);
    }

    for (int b = 0; b < 3; ++b) {
        __syncthreads();    // guards red reads of prev branch vs A overwrite

        // ---- layer 1 (both tiles): elementwise -> A split buffers ----
        #pragma unroll
        for (int i = 0; i < 4; ++i) {
            int g = tid + i * NT;             // 0..1023
            int tile = g >> 9;
            int gg = g & 511;
            int r = gg >> 4, c0 = (gg & 15) * 8;
            float tv = __ldg(t + base + tile * MTILE + r);
            float4 w1a = __ldg((const float4*)(W1 + b*HD + c0));
            float4 w1b = __ldg((const float4*)(W1 + b*HD + c0 + 4));
            float4 c1a = __ldg((const float4*)(b1 + b*HD + c0));
            float4 c1b = __ldg((const float4*)(b1 + b*HD + c0 + 4));
            float wv[8] = {w1a.x,w1a.y,w1a.z,w1a.w,w1b.x,w1b.y,w1b.z,w1b.w};
            float cv[8] = {c1a.x,c1a.y,c1a.z,c1a.w,c1b.x,c1b.y,c1b.z,c1b.w};
            float hv[8], hd[8];
            #pragma unroll
            for (int q = 0; q < 8; ++q) {
                float pre = fmaf(tv, wv[q], cv[q]);
                bool mk = pre > 0.f;
                hv[q] = mk ? pre : 0.f;
                hd[q] = mk ? wv[q] : 0.f;
            }
            uint4 vh, vl, dh;
            split2f_pair(hv[0], hv[1], vh.x, vl.x);
            split2f_pair(hv[2], hv[3], vh.y, vl.y);
            split2f_pair(hv[4], hv[5], vh.z, vl.z);
            split2f_pair(hv[6], hv[7], vh.w, vl.w);
            dh.x = pack_f16_pair(hd[0], hd[1]);
            dh.y = pack_f16_pair(hd[2], hd[3]);
            dh.z = pack_f16_pair(hd[4], hd[5]);
            dh.w = pack_f16_pair(hd[6], hd[7]);
            uint32_t ao = swz8(r, c0 >> 3);
            *(uint4*)(smA + (tile ? OFF_AVH1 : OFF_AVH0) + ao) = vh;
            *(uint4*)(smA + (tile ? OFF_AVL1 : OFF_AVL0) + ao) = vl;
            *(uint4*)(smA + (tile ? OFF_ADH1 : OFF_ADH0) + ao) = dh;
        }
        if (b == 0) CP_WAIT0();
        __syncthreads();

        #pragma unroll 1
        for (int layer = 0; layer < 2; ++layer) {
            const int nxt = 2*b + layer + 1;
            const float* bias = (layer == 0) ? b2 : b3;

            float acc1[4][4], acc2[4][4], acc3[4][4], accd1[4][4];

            #pragma unroll 1
            for (int tile = 0; tile < 2; ++tile) {
                mma_tile(AVH[tile], AVL[tile], ADH[tile], BH, BL,
                         m0, n0, lane, acc1, acc2, acc3, accd1);

                if (layer == 0) {
                    // ---- staged epilogue 2: compute packed results in regs ----
                    uint32_t rvh[8], rvl[8], rdh[8];
                    #pragma unroll
                    for (int h = 0; h < 2; ++h)
                        #pragma unroll
                        for (int nt = 0; nt < 4; ++nt) {
                            int c = n0 + 8*nt + (lane & 3)*2;
                            float2 bb = __ldg((const float2*)(bias + b*HD + c));
                            float p0 = acc1[nt][2*h]   + fmaf(acc2[nt][2*h],   S_DN,
                                         fmaf(acc3[nt][2*h],   S_DN2, bb.x));
                            float p1 = acc1[nt][2*h+1] + fmaf(acc2[nt][2*h+1], S_DN,
                                         fmaf(acc3[nt][2*h+1], S_DN2, bb.y));
                            bool q0 = p0 > 0.f, q1 = p1 > 0.f;
                            float v0 = q0 ? p0 : 0.f, v1 = q1 ? p1 : 0.f;
                            float d0 = q0 ? accd1[nt][2*h]   : 0.f;
                            float d1 = q1 ? accd1[nt][2*h+1] : 0.f;
                            int idx = h*4 + nt;
                            split2f_pair(v0, v1, rvh[idx], rvl[idx]);
                            rdh[idx] = pack_f16_pair(d0, d1);
                        }

                    __syncthreads();   // A[tile] readers done (and, for tile1, B done)

                    if (tile == 1 && nxt < 6) {
                        const uint4* src = (const uint4*)g_Bsplit[nxt];
                        prefetch_level(src,        BH, tid);
                        prefetch_level(src + 2048, BL, tid);
                    }

                    // ---- stores only ----
                    #pragma unroll
                    for (int h = 0; h < 2; ++h)
                        #pragma unroll
                        for (int nt = 0; nt < 4; ++nt) {
                            int row = m0 + 8*h + (lane >> 2);
                            int c = n0 + 8*nt + (lane & 3)*2;
                            int idx = h*4 + nt;
                            uint32_t ao = swz8(row, c >> 3) + ((c & 7) << 1);
                            *(uint32_t*)(smA + (tile ? OFF_AVH1 : OFF_AVH0) + ao) = rvh[idx];
                            *(uint32_t*)(smA + (tile ? OFF_AVL1 : OFF_AVL0) + ao) = rvl[idx];
                            *(uint32_t*)(smA + (tile ? OFF_ADH1 : OFF_ADH0) + ao) = rdh[idx];
                        }
                } else {
                    // ---- staged epilogue 3: compute dots + shuffles in regs ----
                    float2 res[2];
                    #pragma unroll
                    for (int h = 0; h < 2; ++h) {
                        float sv = 0.f, sd = 0.f;
                        #pragma unroll
                        for (int nt = 0; nt < 4; ++nt) {
                            int c = n0 + 8*nt + (lane & 3)*2;
                            float2 bb = __ldg((const float2*)(b3 + b*HD + c));
                            float2 ww = __ldg((const float2*)(W4 + b*HD + c));
                            float p0 = acc1[nt][2*h]   + fmaf(acc2[nt][2*h],   S_DN,
                                         fmaf(acc3[nt][2*h],   S_DN2, bb.x));
                            float p1 = acc1[nt][2*h+1] + fmaf(acc2[nt][2*h+1], S_DN,
                                         fmaf(acc3[nt][2*h+1], S_DN2, bb.y));
                            bool q0 = p0 > 0.f, q1 = p1 > 0.f;
                            sv = fmaf(q0 ? p0 : 0.f, ww.x, sv);
                            sv = fmaf(q1 ? p1 : 0.f, ww.y, sv);
                            sd = fmaf(q0 ? accd1[nt][2*h]   : 0.f, ww.x, sd);
                            sd = fmaf(q1 ? accd1[nt][2*h+1] : 0.f, ww.y, sd);
                        }
                        sv += __shfl_xor_sync(0xffffffffu, sv, 1);
                        sv += __shfl_xor_sync(0xffffffffu, sv, 2);
                        sd += __shfl_xor_sync(0xffffffffu, sd, 1);
                        sd += __shfl_xor_sync(0xffffffffu, sd, 2);
                        res[h] = make_float2(sv, sd);
                    }

                    __syncthreads();   // ADH[tile] readers done -> red alias safe

                    if (tile == 1 && nxt < 6) {
                        const uint4* src = (const uint4*)g_Bsplit[nxt];
                        prefetch_level(src,        BH, tid);
                        prefetch_level(src + 2048, BL, tid);
                    }
                    if (tile == 1 && tid < MTILE) {
                        // out writes for tile 0 (red0 complete since this sync)
                        float2 r0 = red0[tid*4+0], r1 = red0[tid*4+1],
                               r2 = red0[tid*4+2], r3 = red0[tid*4+3];
                        float v  = r0.x + r1.x + r2.x + r3.x + __ldg(b4 + b);
                        float dv = r0.y + r1.y + r2.y + r3.y;
                        float2 h0 = g_head[b][0];
                        float2 h1 = g_head[b][1];
                        float s = (b == 1) ? -1.f : 1.f;
                        float d1 = h1.x - h0.x;
                        float sg1 = (d1 > 0.f) ? 1.f : ((d1 < 0.f) ? -1.f : 0.f);
                        float dsign1 = s * sg1 * h1.y;
                        int n = base + tid;
                        float d = v - h0.x;
                        float vv, ds;
                        if (n == 0) {
                            vv = 0.f;
                            ds = (dsign1 >= 0.f) ? fabsf(dv) : -fabsf(dv);
                        } else {
                            float sg = (d > 0.f) ? 1.f : ((d < 0.f) ? -1.f : 0.f);
                            vv = s * fabsf(d);
                            ds = s * sg * dv;
                        }
                        out[b*N + n]       = vv;
                        out[(3 + b)*N + n] = ds;
                    }

                    // ---- stores only ----
                    float2* red = tile ? red1 : red0;
                    if ((lane & 3) == 0) {
                        #pragma unroll
                        for (int h = 0; h < 2; ++h) {
                            int row = m0 + 8*h + (lane >> 2);
                            red[row*4 + wn] = res[h];
                        }
                    }
                }

                if (tile == 1) {
                    CP_WAIT0();
                }
            }
            __syncthreads();   // A' writes + red1 + next B all in place

            if (layer == 1 && tid < MTILE) {
                // out writes for tile 1
                float2 r0 = red1[tid*4+0], r1 = red1[tid*4+1],
                       r2 = red1[tid*4+2], r3 = red1[tid*4+3];
                float v  = r0.x + r1.x + r2.x + r3.x + __ldg(b4 + b);
                float dv = r0.y + r1.y + r2.y + r3.y;
                float2 h0 = g_head[b][0];
                float2 h1 = g_head[b][1];
                float s = (b == 1) ? -1.f : 1.f;
                float d1 = h1.x - h0.x;
                float sg1 = (d1 > 0.f) ? 1.f : ((d1 < 0.f) ? -1.f : 0.f);
                float dsign1 = s * sg1 * h1.y;
                int n = base + MTILE + tid;
                float d = v - h0.x;
                float vv, ds;
                if (n == 0) {
                    vv = 0.f;
                    ds = (dsign1 >= 0.f) ? fabsf(dv) : -fabsf(dv);
                } else {
                    float sg = (d > 0.f) ? 1.f : ((d < 0.f) ? -1.f : 0.f);
                    vv = s * fabsf(d);
                    ds = s * sg * dv;
                }
                out[b*N + n]       = vv;
                out[(3 + b)*N + n] = ds;
            }
        }
    }
}

// ---------------------------------------------------------------------------
extern "C" void kernel_launch(void* const* d_in, const int* in_sizes, int n_in,
                              void* d_out, int out_size)
{
    const float* t  = (const float*)d_in[0];
    const float* W1 = (const float*)d_in[1];
    const float* b1 = (const float*)d_in[2];
    const float* W2 = (const float*)d_in[3];
    const float* b2 = (const float*)d_in[4];
    const float* W3 = (const float*)d_in[5];
    const float* b3 = (const float*)d_in[6];
    const float* W4 = (const float*)d_in[7];
    const float* b4 = (const float*)d_in[8];
    float* out = (float*)d_out;
    const int N = in_sizes[0];

    const int HEAD_SMEM = HD * HWS * 4;

    cudaFuncSetAttribute(main_kernel, cudaFuncAttributeMaxDynamicSharedMemorySize, MAIN_SMEM);
    cudaFuncSetAttribute(head_kernel, cudaFuncAttributeMaxDynamicSharedMemorySize, HEAD_SMEM);

    prep_kernel<<<6, 256>>>(W2, W3);
    head_kernel<<<1, HD, HEAD_SMEM>>>(t, W1, b1, W2, b2, W3, b3, W4, b4);
    main_kernel<<<N / (2 * MTILE), NT, MAIN_SMEM>>>(t, W1, b1, b2, b3, W4, b4, out, N);
}